// round 9
// baseline (speedup 1.0000x reference)
#include <cuda_runtime.h>
#include <cuda_bf16.h>
#include <math.h>
#include <stdint.h>

#define NROWS 8192
#define DDIM  128
#define INV_T 14.285714285714286f            // 1/0.07 == shift C == row max
#define K2    20.60992915555662f             // log2(e)/0.07

// ---------------- device scratch ----------------
__device__ __nv_bfloat16 g_feats[NROWS * DDIM];   // normalized bf16 features
__device__ float g_S[NROWS];                      // sum_{j!=i} exp(l_ij - C)
__device__ float g_classSum[100 * DDIM];          // per-class feature sums
__device__ int   g_hist[100];                     // class histogram
__device__ int   g_labels[NROWS];

// ---------------- prep: normalize + labels + zero accumulators ----------------
__global__ void prep_norm_kernel(const float* __restrict__ f,
                                 const unsigned int* __restrict__ lw,
                                 float* __restrict__ out) {
    __shared__ int flag;
    int warp = threadIdx.x >> 5;
    int lane = threadIdx.x & 31;
    int row = blockIdx.x * 8 + warp;

    const float4* src = (const float4*)(f + (size_t)row * DDIM);
    float4 v = src[lane];
    float ss = v.x * v.x + v.y * v.y + v.z * v.z + v.w * v.w;
    #pragma unroll
    for (int o = 16; o; o >>= 1) ss += __shfl_xor_sync(0xffffffffu, ss, o);
    float s = 1.0f / fmaxf(sqrtf(ss), 1e-12f);
    __nv_bfloat162* dst = (__nv_bfloat162*)(g_feats + (size_t)row * DDIM);
    dst[lane * 2 + 0] = __floats2bfloat162_rn(v.x * s, v.y * s);
    dst[lane * 2 + 1] = __floats2bfloat162_rn(v.z * s, v.w * s);

    // label dtype sniff: int64 -> odd 32-bit words all zero in first 512 words
    if (threadIdx.x == 0) flag = 0;
    __syncthreads();
    if (lw[2 * threadIdx.x + 1] != 0u) atomicOr(&flag, 1);
    __syncthreads();
    bool is64 = (flag == 0);
    if (threadIdx.x < 8) {
        int i = blockIdx.x * 8 + threadIdx.x;
        g_labels[i] = (int)(is64 ? lw[2 * i] : lw[i]);
        g_S[i] = 0.0f;
    }
    int gid = blockIdx.x * 256 + threadIdx.x;
    if (gid < 100 * DDIM) g_classSum[gid] = 0.0f;
    if (gid < 100) g_hist[gid] = 0;
    if (gid == 0) out[0] = 0.0f;
}

// ---------------- classSum + hist: per-class sums (atomic) ----------------
__global__ void classsum_kernel() {
    int warp = threadIdx.x >> 5;
    int lane = threadIdx.x & 31;
    int i = blockIdx.x * 8 + warp;
    int lab = g_labels[i];
    const __nv_bfloat162* f2 = (const __nv_bfloat162*)(g_feats + (size_t)i * DDIM);
    __nv_bfloat162 a = f2[lane * 2], b = f2[lane * 2 + 1];
    float* cs = g_classSum + lab * DDIM + lane * 4;
    atomicAdd(cs + 0, __low2float(a));
    atomicAdd(cs + 1, __high2float(a));
    atomicAdd(cs + 2, __low2float(b));
    atomicAdd(cs + 3, __high2float(b));
    if (lane == 0) atomicAdd(&g_hist[lab], 1);
}

// ---------------- symmetric fused GEMM + exp-sum epilogue ----------------
// Upper-triangle tiles; each CTA handles up to FOUR adjacent j-tiles in one
// row-strip (544 CTAs). A loaded once per CTA; B double-buffered via cp.async
// (B(t+2) issued after tile t's epilogue, overlapping tile t+1 compute).
__global__ __launch_bounds__(256, 2) void gemm_kernel() {
    extern __shared__ char smem[];
    // [0,32K) A ; [32K,64K) Bbuf0 ; [64K,96K) Bbuf1 ; then rS(512) cS(512)
    float* rS = (float*)(smem + 98304);
    float* cS = (float*)(smem + 98816);

    const int tid  = threadIdx.x;
    const int lane = tid & 31;
    const int warp = tid >> 5;
    const int warp_m = warp >> 1;      // 0..3
    const int warp_n = warp & 1;       // 0..1
    const int groupid = lane >> 2;     // 0..7
    const int quad = lane & 3;         // 0..3

    // ---- decode (row-strip, group-of-4) ----
    int b = blockIdx.x;
    int ti = 0, c = 16;                 // c = ceil((64-ti)/4)
    while (b >= c) { b -= c; ti++; c = (67 - ti) >> 2; }
    const int jt0 = ti + 4 * b;
    const int nt = (64 - jt0 < 4) ? (64 - jt0) : 4;
    const int iBase = ti * 128;

    const unsigned sbase = (unsigned)__cvta_generic_to_shared(smem);
    const uint4* src = (const uint4*)g_feats;   // 16B chunks, 16 per row

    // ---- initial async loads: A + B0 (group), B1 (group) ----
    {
        #pragma unroll
        for (int it = 0; it < 8; it++) {
            int idx = tid + it * 256;               // 0..2047
            int r = idx >> 4, cc = idx & 15;
            unsigned soff = (unsigned)((r * 16 + (cc ^ (r & 7))) * 16);
            asm volatile("cp.async.cg.shared.global [%0], [%1], 16;"
                         :: "r"(sbase + soff),
                            "l"(src + (size_t)(iBase + r) * 16 + cc) : "memory");
            asm volatile("cp.async.cg.shared.global [%0], [%1], 16;"
                         :: "r"(sbase + 32768u + soff),
                            "l"(src + (size_t)(jt0 * 128 + r) * 16 + cc) : "memory");
        }
        asm volatile("cp.async.commit_group;" ::: "memory");
        if (nt > 1) {
            #pragma unroll
            for (int it = 0; it < 8; it++) {
                int idx = tid + it * 256;
                int r = idx >> 4, cc = idx & 15;
                unsigned soff = (unsigned)((r * 16 + (cc ^ (r & 7))) * 16);
                asm volatile("cp.async.cg.shared.global [%0], [%1], 16;"
                             :: "r"(sbase + 65536u + soff),
                                "l"(src + (size_t)((jt0 + 1) * 128 + r) * 16 + cc) : "memory");
            }
            asm volatile("cp.async.commit_group;" ::: "memory");
        }
        if (tid < 128) { rS[tid] = 0.0f; cS[tid] = 0.0f; }
    }

    float rSreg[4] = {0, 0, 0, 0};

    #pragma unroll 1
    for (int t = 0; t < nt; t++) {
        const int jBase = (jt0 + t) * 128;
        const bool diag = (b == 0 && t == 0);
        const unsigned aBase = sbase;
        const unsigned bBase = sbase + 32768u + (unsigned)(t & 1) * 32768u;

        // ensure B(t) resident: at most one younger group may stay pending
        if (t == nt - 1) {
            asm volatile("cp.async.wait_group 0;" ::: "memory");
        } else {
            asm volatile("cp.async.wait_group 1;" ::: "memory");
        }
        __syncthreads();   // tile ready + cS reset visible

        float acc[2][8][4];
        #pragma unroll
        for (int ms = 0; ms < 2; ms++)
            #pragma unroll
            for (int ns = 0; ns < 8; ns++)
                #pragma unroll
                for (int e = 0; e < 4; e++) acc[ms][ns][e] = 0.0f;

        // ---- main K loop: 8 chunks of k16 ----
        #pragma unroll
        for (int kc = 0; kc < 8; kc++) {
            unsigned a_frag[2][4];
            unsigned b_frag[8][2];

            #pragma unroll
            for (int ms = 0; ms < 2; ms++) {
                int r  = warp_m * 32 + ms * 16 + (lane & 15);
                int c8 = kc * 2 + (lane >> 4);
                unsigned addr = aBase + (unsigned)((r * 16 + (c8 ^ (r & 7))) * 16);
                asm volatile(
                    "ldmatrix.sync.aligned.m8n8.x4.shared.b16 {%0,%1,%2,%3}, [%4];"
                    : "=r"(a_frag[ms][0]), "=r"(a_frag[ms][1]),
                      "=r"(a_frag[ms][2]), "=r"(a_frag[ms][3])
                    : "r"(addr));
            }
            #pragma unroll
            for (int np = 0; np < 4; np++) {
                int r  = warp_n * 64 + (np * 2 + ((lane >> 4) & 1)) * 8 + (lane & 7);
                int c8 = kc * 2 + ((lane >> 3) & 1);
                unsigned addr = bBase + (unsigned)((r * 16 + (c8 ^ (r & 7))) * 16);
                asm volatile(
                    "ldmatrix.sync.aligned.m8n8.x4.shared.b16 {%0,%1,%2,%3}, [%4];"
                    : "=r"(b_frag[np * 2][0]), "=r"(b_frag[np * 2][1]),
                      "=r"(b_frag[np * 2 + 1][0]), "=r"(b_frag[np * 2 + 1][1])
                    : "r"(addr));
            }
            #pragma unroll
            for (int ms = 0; ms < 2; ms++)
                #pragma unroll
                for (int ns = 0; ns < 8; ns++) {
                    asm volatile(
                        "mma.sync.aligned.m16n8k16.row.col.f32.bf16.bf16.f32 "
                        "{%0,%1,%2,%3}, {%4,%5,%6,%7}, {%8,%9}, {%0,%1,%2,%3};"
                        : "+f"(acc[ms][ns][0]), "+f"(acc[ms][ns][1]),
                          "+f"(acc[ms][ns][2]), "+f"(acc[ms][ns][3])
                        : "r"(a_frag[ms][0]), "r"(a_frag[ms][1]),
                          "r"(a_frag[ms][2]), "r"(a_frag[ms][3]),
                          "r"(b_frag[ns][0]), "r"(b_frag[ns][1]));
                }
        }

        // ---- epilogue: S only (P is analytic) ----
        #pragma unroll
        for (int ns = 0; ns < 8; ns++) {
            int jl = warp_n * 64 + ns * 8 + quad * 2;
            float cs0 = 0.0f, cs1 = 0.0f;
            #pragma unroll
            for (int ms = 0; ms < 2; ms++) {
                #pragma unroll
                for (int e = 0; e < 4; e++) {
                    int ridx = ms * 2 + (e >> 1);
                    float fv = fmaf(acc[ms][ns][e], K2, -K2);  // log2 scale
                    float ex;
                    asm("ex2.approx.f32 %0, %1;" : "=f"(ex) : "f"(fv));
                    if (diag) {
                        int il = warp_m * 32 + ms * 16 + groupid + (e >> 1) * 8;
                        if (il == jl + (e & 1)) ex = 0.0f;     // exclude self
                    }
                    rSreg[ridx] += ex;
                    if (e & 1) cs1 += ex; else cs0 += ex;
                }
            }
            if (!diag) {
                #pragma unroll
                for (int o = 4; o <= 16; o <<= 1) {
                    cs0 += __shfl_xor_sync(0xffffffffu, cs0, o);
                    cs1 += __shfl_xor_sync(0xffffffffu, cs1, o);
                }
                if (groupid == 0) {
                    atomicAdd(&cS[jl], cs0);
                    atomicAdd(&cS[jl + 1], cs1);
                }
            }
        }

        __syncthreads();   // all warps done with Bbuf(t&1) and cS atomics

        // flush col-side S, reset cS
        if (tid < 128 && !diag) {
            atomicAdd(&g_S[jBase + tid], cS[tid]);
            cS[tid] = 0.0f;
        }

        // prefetch B(t+2) into the buffer tile t just vacated
        if (t + 2 < nt) {
            unsigned pbase = sbase + 32768u + (unsigned)(t & 1) * 32768u;
            #pragma unroll
            for (int it = 0; it < 8; it++) {
                int idx = tid + it * 256;
                int r = idx >> 4, cc = idx & 15;
                unsigned soff = (unsigned)((r * 16 + (cc ^ (r & 7))) * 16);
                asm volatile("cp.async.cg.shared.global [%0], [%1], 16;"
                             :: "r"(pbase + soff),
                                "l"(src + (size_t)((jt0 + t + 2) * 128 + r) * 16 + cc) : "memory");
            }
            asm volatile("cp.async.commit_group;" ::: "memory");
        }
    }

    // ---- row-side flush (once per CTA) ----
    #pragma unroll
    for (int r = 0; r < 4; r++) {
        float s = rSreg[r];
        s += __shfl_xor_sync(0xffffffffu, s, 1);
        s += __shfl_xor_sync(0xffffffffu, s, 2);
        if (quad == 0) {
            int rloc = warp_m * 32 + (r >> 1) * 16 + groupid + (r & 1) * 8;
            atomicAdd(&rS[rloc], s);
        }
    }
    __syncthreads();
    if (tid < 128) atomicAdd(&g_S[iBase + tid], rS[tid]);
}

// ---------------- final loss (32 blocks x 256) ----------------
// loss = (1/N)[ sum_i log(S_i+1e-12) - sum_c (|cs_c|^2 - h_c^2)/(T*(h_c-1)) ]
__global__ void loss_kernel(float* __restrict__ out) {
    __shared__ float red[256];
    int t = threadIdx.x;
    int lane = t & 31;
    int i = blockIdx.x * 256 + t;

    float local = __logf(g_S[i] + 1e-12f);

    // class part: one warp per class (blocks 0..12 cover classes 0..99)
    int gw = blockIdx.x * 8 + (t >> 5);
    if (gw < 100) {
        const float4* cs = (const float4*)(g_classSum + gw * DDIM);
        float4 c = cs[lane];
        float d = c.x * c.x + c.y * c.y + c.z * c.z + c.w * c.w;
        #pragma unroll
        for (int o = 16; o; o >>= 1) d += __shfl_xor_sync(0xffffffffu, d, o);
        if (lane == 0) {
            float h = (float)g_hist[gw];
            if (h > 1.5f) local -= (d - h * h) * INV_T / (h - 1.0f);
        }
    }

    red[t] = local;
    __syncthreads();
    #pragma unroll
    for (int s = 128; s > 0; s >>= 1) {
        if (t < s) red[t] += red[t + s];
        __syncthreads();
    }
    if (t == 0) atomicAdd(out, red[0] / (float)NROWS);
}

// ---------------- launch ----------------
extern "C" void kernel_launch(void* const* d_in, const int* in_sizes, int n_in,
                              void* d_out, int out_size) {
    const float* feats = (const float*)d_in[0];
    const unsigned int* labw = (const unsigned int*)d_in[1];

    cudaFuncSetAttribute(gemm_kernel, cudaFuncAttributeMaxDynamicSharedMemorySize,
                         99328);

    prep_norm_kernel<<<NROWS / 8, 256>>>(feats, labw, (float*)d_out);
    classsum_kernel<<<NROWS / 8, 256>>>();
    gemm_kernel<<<544, 256, 99328>>>();
    loss_kernel<<<NROWS / 256, 256>>>((float*)d_out);
}

// round 10
// speedup vs baseline: 1.5350x; 1.5350x over previous
#include <cuda_runtime.h>
#include <cuda_bf16.h>
#include <math.h>
#include <stdint.h>

#define NROWS 8192
#define DDIM  128
#define INV_T 14.285714285714286f            // 1/0.07 == shift C == row max
#define K2    20.60992915555662f             // log2(e)/0.07

// ---------------- device scratch ----------------
__device__ __nv_bfloat16 g_feats[NROWS * DDIM];   // normalized bf16 features
__device__ float g_S[NROWS];                      // sum_{j!=i} exp(l_ij - C)
__device__ float g_classSum[100 * DDIM];          // per-class feature sums
__device__ int   g_hist[100];                     // class histogram
__device__ int   g_labels[NROWS];

// ---------------- prep: normalize (2 rows/warp) + labels + zero accum ----------------
__global__ void prep_norm_kernel(const float* __restrict__ f,
                                 const unsigned int* __restrict__ lw,
                                 float* __restrict__ out) {
    __shared__ int flag;
    int warp = threadIdx.x >> 5;
    int lane = threadIdx.x & 31;
    int r0 = blockIdx.x * 16 + warp * 2;
    int r1 = r0 + 1;

    const float4* s0 = (const float4*)(f + (size_t)r0 * DDIM);
    const float4* s1 = (const float4*)(f + (size_t)r1 * DDIM);
    float4 v0 = s0[lane];
    float4 v1 = s1[lane];
    float ss0 = v0.x * v0.x + v0.y * v0.y + v0.z * v0.z + v0.w * v0.w;
    float ss1 = v1.x * v1.x + v1.y * v1.y + v1.z * v1.z + v1.w * v1.w;
    #pragma unroll
    for (int o = 16; o; o >>= 1) {
        ss0 += __shfl_xor_sync(0xffffffffu, ss0, o);
        ss1 += __shfl_xor_sync(0xffffffffu, ss1, o);
    }
    float sc0 = 1.0f / fmaxf(sqrtf(ss0), 1e-12f);
    float sc1 = 1.0f / fmaxf(sqrtf(ss1), 1e-12f);
    __nv_bfloat162* d0 = (__nv_bfloat162*)(g_feats + (size_t)r0 * DDIM);
    __nv_bfloat162* d1 = (__nv_bfloat162*)(g_feats + (size_t)r1 * DDIM);
    d0[lane * 2 + 0] = __floats2bfloat162_rn(v0.x * sc0, v0.y * sc0);
    d0[lane * 2 + 1] = __floats2bfloat162_rn(v0.z * sc0, v0.w * sc0);
    d1[lane * 2 + 0] = __floats2bfloat162_rn(v1.x * sc1, v1.y * sc1);
    d1[lane * 2 + 1] = __floats2bfloat162_rn(v1.z * sc1, v1.w * sc1);

    // label dtype sniff: int64 -> odd 32-bit words all zero in first 512 words
    if (threadIdx.x == 0) flag = 0;
    __syncthreads();
    if (lw[2 * threadIdx.x + 1] != 0u) atomicOr(&flag, 1);
    __syncthreads();
    bool is64 = (flag == 0);
    if (threadIdx.x < 16) {
        int i = blockIdx.x * 16 + threadIdx.x;
        g_labels[i] = (int)(is64 ? lw[2 * i] : lw[i]);
        g_S[i] = 0.0f;
    }
    int gid = blockIdx.x * 256 + threadIdx.x;
    if (gid < 100 * DDIM) g_classSum[gid] = 0.0f;
    if (gid < 100) g_hist[gid] = 0;
    if (gid == 0) out[0] = 0.0f;
}

// ---------------- classSum + hist: per-class sums (atomic) ----------------
__global__ void classsum_kernel() {
    int warp = threadIdx.x >> 5;
    int lane = threadIdx.x & 31;
    int i = blockIdx.x * 8 + warp;
    int lab = g_labels[i];
    const __nv_bfloat162* f2 = (const __nv_bfloat162*)(g_feats + (size_t)i * DDIM);
    __nv_bfloat162 a = f2[lane * 2], b = f2[lane * 2 + 1];
    float* cs = g_classSum + lab * DDIM + lane * 4;
    atomicAdd(cs + 0, __low2float(a));
    atomicAdd(cs + 1, __high2float(a));
    atomicAdd(cs + 2, __low2float(b));
    atomicAdd(cs + 3, __high2float(b));
    if (lane == 0) atomicAdd(&g_hist[lab], 1);
}

// ---------------- symmetric fused GEMM + exp-sum epilogue (R7 shape) ----------------
// Upper-triangle tiles; each CTA handles a PAIR of adjacent j-tiles in one
// row-strip (1056 CTAs). A loaded once per CTA; B double-buffered via
// cp.async so tile-1's load overlaps tile-0's compute.
__global__ __launch_bounds__(256, 2) void gemm_kernel() {
    extern __shared__ char smem[];
    // [0,32K) A ; [32K,64K) B0 ; [64K,96K) B1 ; then rS(512) cS(512)
    float* rS = (float*)(smem + 98304);
    float* cS = (float*)(smem + 98816);

    const int tid  = threadIdx.x;
    const int lane = tid & 31;
    const int warp = tid >> 5;
    const int warp_m = warp >> 1;      // 0..3
    const int warp_n = warp & 1;       // 0..1
    const int groupid = lane >> 2;     // 0..7
    const int quad = lane & 3;         // 0..3

    // ---- decode (row-strip, pair) ----
    int b = blockIdx.x;
    int ti = 0, c = 32;                 // c = ceil((64-ti)/2)
    while (b >= c) { b -= c; ti++; c = (65 - ti) >> 1; }
    const int jt0 = ti + 2 * b;
    const int ntile = (jt0 + 1 < 64) ? 2 : 1;
    const int iBase = ti * 128;

    const unsigned sbase = (unsigned)__cvta_generic_to_shared(smem);

    // ---- async tile loads: A + B0 (group0), B1 (group1) ----
    {
        const uint4* src = (const uint4*)g_feats;   // 16B chunks, 16 per row
        #pragma unroll
        for (int it = 0; it < 8; it++) {
            int idx = tid + it * 256;               // 0..2047
            int r = idx >> 4, cc = idx & 15;
            unsigned soff = (unsigned)((r * 16 + (cc ^ (r & 7))) * 16);
            asm volatile("cp.async.cg.shared.global [%0], [%1], 16;"
                         :: "r"(sbase + soff),
                            "l"(src + (size_t)(iBase + r) * 16 + cc) : "memory");
            asm volatile("cp.async.cg.shared.global [%0], [%1], 16;"
                         :: "r"(sbase + 32768u + soff),
                            "l"(src + (size_t)(jt0 * 128 + r) * 16 + cc) : "memory");
        }
        asm volatile("cp.async.commit_group;" ::: "memory");
        if (ntile == 2) {
            #pragma unroll
            for (int it = 0; it < 8; it++) {
                int idx = tid + it * 256;
                int r = idx >> 4, cc = idx & 15;
                unsigned soff = (unsigned)((r * 16 + (cc ^ (r & 7))) * 16);
                asm volatile("cp.async.cg.shared.global [%0], [%1], 16;"
                             :: "r"(sbase + 65536u + soff),
                                "l"(src + (size_t)((jt0 + 1) * 128 + r) * 16 + cc) : "memory");
            }
            asm volatile("cp.async.commit_group;" ::: "memory");
            asm volatile("cp.async.wait_group 1;" ::: "memory");
        } else {
            asm volatile("cp.async.wait_group 0;" ::: "memory");
        }
        if (tid < 128) { rS[tid] = 0.0f; cS[tid] = 0.0f; }
    }
    __syncthreads();

    float rSreg[4] = {0, 0, 0, 0};

    #pragma unroll 1
    for (int t = 0; t < ntile; t++) {
        const int jBase = (jt0 + t) * 128;
        const bool diag = (b == 0 && t == 0);
        const unsigned aBase = sbase;
        const unsigned bBase = sbase + 32768u + (unsigned)t * 32768u;

        if (t == 1) {
            asm volatile("cp.async.wait_group 0;" ::: "memory");
            __syncthreads();   // Bs1 ready + cS reset visible
        }

        float acc[2][8][4];
        #pragma unroll
        for (int ms = 0; ms < 2; ms++)
            #pragma unroll
            for (int ns = 0; ns < 8; ns++)
                #pragma unroll
                for (int e = 0; e < 4; e++) acc[ms][ns][e] = 0.0f;

        // ---- main K loop: 8 chunks of k16 ----
        #pragma unroll
        for (int kc = 0; kc < 8; kc++) {
            unsigned a_frag[2][4];
            unsigned b_frag[8][2];

            #pragma unroll
            for (int ms = 0; ms < 2; ms++) {
                int r  = warp_m * 32 + ms * 16 + (lane & 15);
                int c8 = kc * 2 + (lane >> 4);
                unsigned addr = aBase + (unsigned)((r * 16 + (c8 ^ (r & 7))) * 16);
                asm volatile(
                    "ldmatrix.sync.aligned.m8n8.x4.shared.b16 {%0,%1,%2,%3}, [%4];"
                    : "=r"(a_frag[ms][0]), "=r"(a_frag[ms][1]),
                      "=r"(a_frag[ms][2]), "=r"(a_frag[ms][3])
                    : "r"(addr));
            }
            #pragma unroll
            for (int np = 0; np < 4; np++) {
                int r  = warp_n * 64 + (np * 2 + ((lane >> 4) & 1)) * 8 + (lane & 7);
                int c8 = kc * 2 + ((lane >> 3) & 1);
                unsigned addr = bBase + (unsigned)((r * 16 + (c8 ^ (r & 7))) * 16);
                asm volatile(
                    "ldmatrix.sync.aligned.m8n8.x4.shared.b16 {%0,%1,%2,%3}, [%4];"
                    : "=r"(b_frag[np * 2][0]), "=r"(b_frag[np * 2][1]),
                      "=r"(b_frag[np * 2 + 1][0]), "=r"(b_frag[np * 2 + 1][1])
                    : "r"(addr));
            }
            #pragma unroll
            for (int ms = 0; ms < 2; ms++)
                #pragma unroll
                for (int ns = 0; ns < 8; ns++) {
                    asm volatile(
                        "mma.sync.aligned.m16n8k16.row.col.f32.bf16.bf16.f32 "
                        "{%0,%1,%2,%3}, {%4,%5,%6,%7}, {%8,%9}, {%0,%1,%2,%3};"
                        : "+f"(acc[ms][ns][0]), "+f"(acc[ms][ns][1]),
                          "+f"(acc[ms][ns][2]), "+f"(acc[ms][ns][3])
                        : "r"(a_frag[ms][0]), "r"(a_frag[ms][1]),
                          "r"(a_frag[ms][2]), "r"(a_frag[ms][3]),
                          "r"(b_frag[ns][0]), "r"(b_frag[ns][1]));
                }
        }

        // ---- epilogue: S only (P is analytic) ----
        #pragma unroll
        for (int ns = 0; ns < 8; ns++) {
            int jl = warp_n * 64 + ns * 8 + quad * 2;
            float cs0 = 0.0f, cs1 = 0.0f;
            #pragma unroll
            for (int ms = 0; ms < 2; ms++) {
                #pragma unroll
                for (int e = 0; e < 4; e++) {
                    int ridx = ms * 2 + (e >> 1);
                    float fv = fmaf(acc[ms][ns][e], K2, -K2);  // log2 scale
                    float ex;
                    asm("ex2.approx.f32 %0, %1;" : "=f"(ex) : "f"(fv));
                    if (diag) {
                        int il = warp_m * 32 + ms * 16 + groupid + (e >> 1) * 8;
                        if (il == jl + (e & 1)) ex = 0.0f;     // exclude self
                    }
                    rSreg[ridx] += ex;
                    if (e & 1) cs1 += ex; else cs0 += ex;
                }
            }
            if (!diag) {
                #pragma unroll
                for (int o = 4; o <= 16; o <<= 1) {
                    cs0 += __shfl_xor_sync(0xffffffffu, cs0, o);
                    cs1 += __shfl_xor_sync(0xffffffffu, cs1, o);
                }
                if (groupid == 0) {
                    atomicAdd(&cS[jl], cs0);
                    atomicAdd(&cS[jl + 1], cs1);
                }
            }
        }

        __syncthreads();
        if (tid < 128 && !diag) {
            atomicAdd(&g_S[jBase + tid], cS[tid]);
            cS[tid] = 0.0f;
        }
    }

    // ---- row-side flush (once per CTA) ----
    #pragma unroll
    for (int r = 0; r < 4; r++) {
        float s = rSreg[r];
        s += __shfl_xor_sync(0xffffffffu, s, 1);
        s += __shfl_xor_sync(0xffffffffu, s, 2);
        if (quad == 0) {
            int rloc = warp_m * 32 + (r >> 1) * 16 + groupid + (r & 1) * 8;
            atomicAdd(&rS[rloc], s);
        }
    }
    __syncthreads();
    if (tid < 128) atomicAdd(&g_S[iBase + tid], rS[tid]);
}

// ---------------- final loss (64 blocks x 128) ----------------
// loss = (1/N)[ sum_i log(S_i+1e-12) - sum_c (|cs_c|^2 - h_c^2)/(T*(h_c-1)) ]
__global__ void loss_kernel(float* __restrict__ out) {
    __shared__ float red[128];
    int t = threadIdx.x;
    int lane = t & 31;
    int i = blockIdx.x * 128 + t;

    float local = __logf(g_S[i] + 1e-12f);

    // class part: one warp per class (first 100 of 256 warps)
    int gw = blockIdx.x * 4 + (t >> 5);
    if (gw < 100) {
        const float4* cs = (const float4*)(g_classSum + gw * DDIM);
        float4 c = cs[lane];
        float d = c.x * c.x + c.y * c.y + c.z * c.z + c.w * c.w;
        #pragma unroll
        for (int o = 16; o; o >>= 1) d += __shfl_xor_sync(0xffffffffu, d, o);
        if (lane == 0) {
            float h = (float)g_hist[gw];
            if (h > 1.5f) local -= (d - h * h) * INV_T / (h - 1.0f);
        }
    }

    red[t] = local;
    __syncthreads();
    #pragma unroll
    for (int s = 64; s > 0; s >>= 1) {
        if (t < s) red[t] += red[t + s];
        __syncthreads();
    }
    if (t == 0) atomicAdd(out, red[0] / (float)NROWS);
}

// ---------------- launch ----------------
extern "C" void kernel_launch(void* const* d_in, const int* in_sizes, int n_in,
                              void* d_out, int out_size) {
    const float* feats = (const float*)d_in[0];
    const unsigned int* labw = (const unsigned int*)d_in[1];

    cudaFuncSetAttribute(gemm_kernel, cudaFuncAttributeMaxDynamicSharedMemorySize,
                         99328);

    prep_norm_kernel<<<NROWS / 16, 256>>>(feats, labw, (float*)d_out);
    classsum_kernel<<<NROWS / 8, 256>>>();
    gemm_kernel<<<1056, 256, 99328>>>();
    loss_kernel<<<NROWS / 128, 128>>>((float*)d_out);
}